// round 1
// baseline (speedup 1.0000x reference)
#include <cuda_runtime.h>
#include <math.h>

// Shapes (fixed by problem)
#define B_   512
#define N_   225   // centers = HW
#define C_   256
#define V_   256
#define M_   225   // HW
#define OUTC 512   // vd + 256 channels in mem_out

// d_out layout: mem_out [B,512,225] floats, then p [B,225,225] floats.

// ---------------------------------------------------------------------------
// GEMM1: S[b,n,m] = (sum_c m_in[b,n,c]*q_in[b,c,m]) / 16 * mask(n,m)
// 64x64 output tile, K-chunk 16, 256 threads, 4x4 per-thread micro-tile.
// ---------------------------------------------------------------------------
__global__ __launch_bounds__(256) void k_scores(const float* __restrict__ m_in,
                                                const float* __restrict__ q_in,
                                                float* __restrict__ p)
{
    __shared__ float As[16][68];   // [k][n] transposed A tile (padded)
    __shared__ float Bs[16][68];   // [k][m]
    __shared__ float PW[15];       // 0.92^d table

    const int tid = threadIdx.x;
    if (tid < 15) {
        float v = 1.0f;
        for (int i = 0; i < tid; i++) v *= 0.92f;
        PW[tid] = v;
    }

    const int b  = blockIdx.z;
    const int n0 = blockIdx.y * 64;
    const int m0 = blockIdx.x * 64;
    const int tx = tid & 15;
    const int ty = tid >> 4;

    const float* A = m_in + (size_t)b * N_ * C_;   // [n][c]
    const float* Q = q_in + (size_t)b * C_ * M_;   // [c][m]

    float acc[4][4] = {};

    const int lr = tid >> 4;     // A-load: row within tile group
    const int lk = tid & 15;     // A-load: k
    const int bk = tid >> 6;     // B-load: k group (0..3)
    const int bm = tid & 63;     // B-load: m within tile

    for (int c0 = 0; c0 < C_; c0 += 16) {
        __syncthreads();
        #pragma unroll
        for (int ps = 0; ps < 4; ps++) {
            int i = lr + ps * 16;
            int n = n0 + i;
            As[lk][i] = (n < N_) ? A[(size_t)n * C_ + c0 + lk] : 0.0f;
        }
        #pragma unroll
        for (int ps = 0; ps < 4; ps++) {
            int k = bk + ps * 4;
            int m = m0 + bm;
            Bs[k][bm] = (m < M_) ? Q[(size_t)(c0 + k) * M_ + m] : 0.0f;
        }
        __syncthreads();
        #pragma unroll
        for (int k = 0; k < 16; k++) {
            float4 a = *(const float4*)&As[k][ty * 4];
            float4 q4 = *(const float4*)&Bs[k][tx * 4];
            acc[0][0] += a.x * q4.x; acc[0][1] += a.x * q4.y;
            acc[0][2] += a.x * q4.z; acc[0][3] += a.x * q4.w;
            acc[1][0] += a.y * q4.x; acc[1][1] += a.y * q4.y;
            acc[1][2] += a.y * q4.z; acc[1][3] += a.y * q4.w;
            acc[2][0] += a.z * q4.x; acc[2][1] += a.z * q4.y;
            acc[2][2] += a.z * q4.z; acc[2][3] += a.z * q4.w;
            acc[3][0] += a.w * q4.x; acc[3][1] += a.w * q4.y;
            acc[3][2] += a.w * q4.z; acc[3][3] += a.w * q4.w;
        }
    }

    const float invs = 0.0625f;   // 1/sqrt(256)
    #pragma unroll
    for (int r = 0; r < 4; r++) {
        int n = n0 + ty * 4 + r;
        if (n >= N_) continue;
        int xn = n / 15, yn = n % 15;
        #pragma unroll
        for (int s = 0; s < 4; s++) {
            int m = m0 + tx * 4 + s;
            if (m >= M_) continue;
            int xm = m / 15, ym = m % 15;
            int dx = xn - xm; dx = dx < 0 ? -dx : dx;
            int dy = yn - ym; dy = dy < 0 ? -dy : dy;
            p[((size_t)b * N_ + n) * M_ + m] = acc[r][s] * invs * PW[dx] * PW[dy];
        }
    }
}

// ---------------------------------------------------------------------------
// Softmax over centers axis (n), in place on p[b,:,m]. One block per batch,
// thread m owns one column; loads are coalesced across m. Online max+sum,
// then one normalize pass.
// ---------------------------------------------------------------------------
__global__ __launch_bounds__(256) void k_softmax(float* __restrict__ p)
{
    const int b = blockIdx.x;
    const int m = threadIdx.x;
    if (m >= M_) return;
    float* col = p + (size_t)b * N_ * M_ + m;

    float mx = -1e30f;
    float s  = 0.0f;
    for (int n = 0; n < N_; n++) {
        float x = col[(size_t)n * M_];
        float nmx = fmaxf(mx, x);
        s = s * __expf(mx - nmx) + __expf(x - nmx);
        mx = nmx;
    }
    float inv = 1.0f / s;
    for (int n = 0; n < N_; n++) {
        float x = col[(size_t)n * M_];
        col[(size_t)n * M_] = __expf(x - mx) * inv;
    }
}

// ---------------------------------------------------------------------------
// GEMM2: mem[b,v,m] = sum_n m_out[b,n,v] * p[b,n,m]
// Both operands already k(=n)-major for the tile loads; no transpose needed.
// ---------------------------------------------------------------------------
__global__ __launch_bounds__(256) void k_mem(const float* __restrict__ m_out,
                                             const float* __restrict__ p,
                                             float* __restrict__ out)
{
    __shared__ float As[16][68];   // [k=n][v]
    __shared__ float Bs[16][68];   // [k=n][m]

    const int tid = threadIdx.x;
    const int b  = blockIdx.z;
    const int v0 = blockIdx.y * 64;
    const int m0 = blockIdx.x * 64;
    const int tx = tid & 15;
    const int ty = tid >> 4;

    const float* A = m_out + (size_t)b * N_ * V_;   // [n][v]
    const float* P = p + (size_t)b * N_ * M_;       // [n][m]

    float acc[4][4] = {};
    const int bk = tid >> 6;
    const int bm = tid & 63;

    for (int n0 = 0; n0 < N_; n0 += 16) {
        __syncthreads();
        #pragma unroll
        for (int ps = 0; ps < 4; ps++) {
            int k = bk + ps * 4;
            int n = n0 + k;
            As[k][bm] = (n < N_) ? A[(size_t)n * V_ + v0 + bm] : 0.0f;
            Bs[k][bm] = (n < N_ && (m0 + bm) < M_) ? P[(size_t)n * M_ + m0 + bm] : 0.0f;
        }
        __syncthreads();
        #pragma unroll
        for (int k = 0; k < 16; k++) {
            float4 a = *(const float4*)&As[k][ty * 4];
            float4 q4 = *(const float4*)&Bs[k][tx * 4];
            acc[0][0] += a.x * q4.x; acc[0][1] += a.x * q4.y;
            acc[0][2] += a.x * q4.z; acc[0][3] += a.x * q4.w;
            acc[1][0] += a.y * q4.x; acc[1][1] += a.y * q4.y;
            acc[1][2] += a.y * q4.z; acc[1][3] += a.y * q4.w;
            acc[2][0] += a.z * q4.x; acc[2][1] += a.z * q4.y;
            acc[2][2] += a.z * q4.z; acc[2][3] += a.z * q4.w;
            acc[3][0] += a.w * q4.x; acc[3][1] += a.w * q4.y;
            acc[3][2] += a.w * q4.z; acc[3][3] += a.w * q4.w;
        }
    }

    #pragma unroll
    for (int r = 0; r < 4; r++) {
        int v = v0 + ty * 4 + r;   // v always < 256
        #pragma unroll
        for (int s = 0; s < 4; s++) {
            int m = m0 + tx * 4 + s;
            if (m < M_)
                out[((size_t)b * OUTC + v) * M_ + m] = acc[r][s];
        }
    }
}

// ---------------------------------------------------------------------------
// Concat copy: mem_out[:, 256:512, :] = q_out. q_out is fully contiguous;
// out offset = idx + (b+1)*57600 with b = idx/57600. float4 vectorized.
// ---------------------------------------------------------------------------
__global__ __launch_bounds__(256) void k_copy(const float4* __restrict__ q,
                                              float* __restrict__ out)
{
    const int TOT4 = (B_ * 256 * M_) / 4;   // 7372800
    int i = blockIdx.x * blockDim.x + threadIdx.x;
    if (i >= TOT4) return;
    int b = i / 14400;                       // 57600/4
    float4 v = q[i];
    *(float4*)(out + (size_t)(b + 1) * 57600 + (size_t)i * 4) = v;
}

// ---------------------------------------------------------------------------
extern "C" void kernel_launch(void* const* d_in, const int* in_sizes, int n_in,
                              void* d_out, int out_size)
{
    const float* m_in  = (const float*)d_in[0];
    const float* m_out = (const float*)d_in[1];
    const float* q_in  = (const float*)d_in[2];
    const float* q_out = (const float*)d_in[3];
    float* out = (float*)d_out;
    float* p   = out + (size_t)B_ * OUTC * M_;   // p region after mem_out

    dim3 g1(4, 4, B_);
    k_scores<<<g1, 256>>>(m_in, q_in, p);
    k_softmax<<<B_, 256>>>(p);
    dim3 g2(4, 4, B_);
    k_mem<<<g2, 256>>>(m_out, p, out);
    const int TOT4 = (B_ * 256 * M_) / 4;
    k_copy<<<(TOT4 + 255) / 256, 256>>>((const float4*)q_out, out);
}